// round 2
// baseline (speedup 1.0000x reference)
#include <cuda_runtime.h>

typedef unsigned long long u64;

#define NBLK  128
#define NTHR  256
#define ROWS  64
#define HPAD  132
#define NSTEP 49

__device__ __forceinline__ u64 ffma2(u64 a, u64 b, u64 c) {
    u64 r;
    asm("fma.rn.f32x2 %0, %1, %2, %3;" : "=l"(r) : "l"(a), "l"(b), "l"(c));
    return r;
}
__device__ __forceinline__ u64 pk2(float lo, float hi) {
    u64 r;
    asm("mov.b64 %0, {%1, %2};" : "=l"(r) : "f"(lo), "f"(hi));
    return r;
}
__device__ __forceinline__ float sum2(u64 v) {
    float lo, hi;
    asm("mov.b64 {%0, %1}, %2;" : "=f"(lo), "=f"(hi) : "l"(v));
    return lo + hi;
}
__device__ __forceinline__ float sigm(float x) {
    return __fdividef(1.0f, 1.0f + __expf(-x));
}
__device__ __forceinline__ float tanh_f(float x) {
    float ax = fabsf(x);
    float e  = __expf(-2.0f * ax);
    float r  = __fdividef(1.0f - e, 1.0f + e);
    return copysignf(r, x);
}

// one 128->128 encoder layer: reads ha (all rows), writes ha (own tile)
__device__ __forceinline__ void enc_layer128(const float* __restrict__ w,
                                             const float* __restrict__ b,
                                             float* ha, int p, int t, bool relu_on) {
    float acc[8][4];
    #pragma unroll
    for (int uu = 0; uu < 8; ++uu)
        #pragma unroll
        for (int m = 0; m < 4; ++m) acc[uu][m] = 0.0f;

    const float4* w4 = (const float4*)w;
    for (int k4 = 0; k4 < 32; ++k4) {
        float xa[4][4];
        #pragma unroll
        for (int m = 0; m < 4; ++m) {
            float4 v = *(const float4*)&ha[(p + 16*m)*HPAD + k4*4];
            xa[m][0] = v.x; xa[m][1] = v.y; xa[m][2] = v.z; xa[m][3] = v.w;
        }
        #pragma unroll
        for (int kk = 0; kk < 4; ++kk) {
            #pragma unroll
            for (int ub = 0; ub < 2; ++ub) {
                float4 wv = __ldg(&w4[(k4*4 + kk)*32 + t*2 + ub]);
                #pragma unroll
                for (int m = 0; m < 4; ++m) {
                    acc[ub*4+0][m] = fmaf(wv.x, xa[m][kk], acc[ub*4+0][m]);
                    acc[ub*4+1][m] = fmaf(wv.y, xa[m][kk], acc[ub*4+1][m]);
                    acc[ub*4+2][m] = fmaf(wv.z, xa[m][kk], acc[ub*4+2][m]);
                    acc[ub*4+3][m] = fmaf(wv.w, xa[m][kk], acc[ub*4+3][m]);
                }
            }
        }
    }
    __syncthreads();   // all reads of ha done
    #pragma unroll
    for (int uu = 0; uu < 8; ++uu) {
        int u = t*8 + uu;
        float bv = __ldg(&b[u]);
        #pragma unroll
        for (int m = 0; m < 4; ++m) {
            float v = acc[uu][m] + bv;
            ha[(p + 16*m)*HPAD + u] = relu_on ? fmaxf(v, 0.0f) : v;
        }
    }
    __syncthreads();
}

__global__ void __launch_bounds__(NTHR, 1)
gru_kernel(const float* __restrict__ x,
           const float* __restrict__ ew0, const float* __restrict__ eb0,
           const float* __restrict__ ew1, const float* __restrict__ eb1,
           const float* __restrict__ ew2, const float* __restrict__ eb2,
           const float* __restrict__ wih, const float* __restrict__ whh,
           const float* __restrict__ bih, const float* __restrict__ bhh,
           const float* __restrict__ dw0, const float* __restrict__ db0,
           const float* __restrict__ dw1, const float* __restrict__ db1,
           float* __restrict__ out) {
    __shared__ float ha[ROWS * HPAD];      // 8448 floats
    __shared__ float dw0t[16 * 128];       // 2048  (transposed decoder w0)
    __shared__ float wihs[384], bihs[384], bhhs[384];
    __shared__ float dw1s[16], db0s[16];
    __shared__ float xps[ROWS];
    __shared__ float outp[4][ROWS];
    __shared__ float db1s;

    const int tid  = threadIdx.x;
    const int p    = tid & 15;     // rows p, p+16, p+32, p+48
    const int t    = tid >> 4;     // units [t*8, t*8+8)
    const int row0 = blockIdx.x * ROWS;

    // ---- init: small weights to smem, output col 0 = zeros, xprev = 0 ----
    for (int j = tid; j < 384; j += NTHR) {
        wihs[j] = wih[j]; bihs[j] = bih[j]; bhhs[j] = bhh[j];
    }
    for (int j = tid; j < 16*128; j += NTHR) {
        int i = j >> 7, u = j & 127;
        dw0t[j] = dw0[u*16 + i];
    }
    if (tid < 16) { dw1s[tid] = dw1[tid]; db0s[tid] = db0[tid]; }
    if (tid == 0) db1s = db1[0];
    if (tid < ROWS) {
        xps[tid] = 0.0f;
        out[(row0 + tid)*50] = 0.0f;
    }

    // ---- encoder layer 0: x[256] -> ha[128] (relu) ----
    {
        float acc[8][4];
        #pragma unroll
        for (int uu = 0; uu < 8; ++uu)
            #pragma unroll
            for (int m = 0; m < 4; ++m) acc[uu][m] = 0.0f;

        const float4* x4  = (const float4*)x;    // 64 float4 per row
        const float4* w04 = (const float4*)ew0;  // 32 float4 per k-row
        for (int k4 = 0; k4 < 64; ++k4) {
            float xa[4][4];
            #pragma unroll
            for (int m = 0; m < 4; ++m) {
                float4 v = __ldg(&x4[(u64)(row0 + p + 16*m)*64 + k4]);
                xa[m][0] = v.x; xa[m][1] = v.y; xa[m][2] = v.z; xa[m][3] = v.w;
            }
            #pragma unroll
            for (int kk = 0; kk < 4; ++kk) {
                #pragma unroll
                for (int ub = 0; ub < 2; ++ub) {
                    float4 wv = __ldg(&w04[(k4*4 + kk)*32 + t*2 + ub]);
                    #pragma unroll
                    for (int m = 0; m < 4; ++m) {
                        acc[ub*4+0][m] = fmaf(wv.x, xa[m][kk], acc[ub*4+0][m]);
                        acc[ub*4+1][m] = fmaf(wv.y, xa[m][kk], acc[ub*4+1][m]);
                        acc[ub*4+2][m] = fmaf(wv.z, xa[m][kk], acc[ub*4+2][m]);
                        acc[ub*4+3][m] = fmaf(wv.w, xa[m][kk], acc[ub*4+3][m]);
                    }
                }
            }
        }
        __syncthreads();   // init writes done before any smem use below anyway
        #pragma unroll
        for (int uu = 0; uu < 8; ++uu) {
            int u = t*8 + uu;
            float bv = __ldg(&eb0[u]);
            #pragma unroll
            for (int m = 0; m < 4; ++m)
                ha[(p + 16*m)*HPAD + u] = fmaxf(acc[uu][m] + bv, 0.0f);
        }
        __syncthreads();
    }

    // ---- encoder layers 1 (relu) and 2 (linear) ----
    enc_layer128(ew1, eb1, ha, p, t, true);
    enc_layer128(ew2, eb2, ha, p, t, false);

    // ---- GRU + decoder, 49 steps ----
    const float4* whh4 = (const float4*)whh;   // 32 float4 per gate-unit row
    const int drow = tid & 63;                 // decoder row
    const int ic   = tid >> 6;                 // decoder i-chunk (4 outputs of 16)

    for (int s = 0; s < NSTEP; ++s) {
        float hnew[32];

        #pragma unroll
        for (int half = 0; half < 2; ++half) {
            u64 acc2[3][4][4];
            #pragma unroll
            for (int g = 0; g < 3; ++g)
                #pragma unroll
                for (int uu = 0; uu < 4; ++uu)
                    #pragma unroll
                    for (int m = 0; m < 4; ++m) acc2[g][uu][m] = pk2(0.0f, 0.0f);

            for (int k4 = 0; k4 < 32; ++k4) {
                u64 hlo[4], hhi[4];
                #pragma unroll
                for (int m = 0; m < 4; ++m) {
                    float4 v = *(const float4*)&ha[(p + 16*m)*HPAD + k4*4];
                    hlo[m] = pk2(v.x, v.y);
                    hhi[m] = pk2(v.z, v.w);
                }
                #pragma unroll
                for (int uu = 0; uu < 4; ++uu) {
                    int u = t*8 + half*4 + uu;
                    #pragma unroll
                    for (int g = 0; g < 3; ++g) {
                        float4 wv = __ldg(&whh4[(g*128 + u)*32 + k4]);
                        u64 wlo = pk2(wv.x, wv.y);
                        u64 whi = pk2(wv.z, wv.w);
                        #pragma unroll
                        for (int m = 0; m < 4; ++m) {
                            acc2[g][uu][m] = ffma2(wlo, hlo[m], acc2[g][uu][m]);
                            acc2[g][uu][m] = ffma2(whi, hhi[m], acc2[g][uu][m]);
                        }
                    }
                }
            }

            // epilogue for this half: activations + new hidden (registers only)
            #pragma unroll
            for (int uu = 0; uu < 4; ++uu) {
                int u = t*8 + half*4 + uu;
                float wir = wihs[u], wiz = wihs[128 + u], win = wihs[256 + u];
                float br  = bihs[u]       + bhhs[u];
                float bz  = bihs[128 + u] + bhhs[128 + u];
                float bni = bihs[256 + u];
                float bnh = bhhs[256 + u];
                #pragma unroll
                for (int m = 0; m < 4; ++m) {
                    int row = p + 16*m;
                    float xp   = xps[row];
                    float hold = ha[row*HPAD + u];
                    float rg  = sigm(sum2(acc2[0][uu][m]) + fmaf(xp, wir, br));
                    float zg  = sigm(sum2(acc2[1][uu][m]) + fmaf(xp, wiz, bz));
                    float ghn = sum2(acc2[2][uu][m]) + bnh;
                    float ng  = tanh_f(fmaf(xp, win, bni) + rg * ghn);
                    hnew[half*16 + uu*4 + m] = (1.0f - zg)*ng + zg*hold;
                }
            }
        }

        __syncthreads();   // everyone finished reading old h
        #pragma unroll
        for (int half = 0; half < 2; ++half)
            #pragma unroll
            for (int uu = 0; uu < 4; ++uu)
                #pragma unroll
                for (int m = 0; m < 4; ++m)
                    ha[(p + 16*m)*HPAD + t*8 + half*4 + uu] = hnew[half*16 + uu*4 + m];
        __syncthreads();   // new h visible

        // ---- decoder: d = relu(h @ dw0 + db0); po = partial of d @ dw1 ----
        {
            const float4* hr4  = (const float4*)&ha[drow * HPAD];
            const float4* dwt4 = (const float4*)dw0t;
            float dacc[4] = {0.0f, 0.0f, 0.0f, 0.0f};
            for (int k4 = 0; k4 < 32; ++k4) {
                float4 hv = hr4[k4];
                #pragma unroll
                for (int ii = 0; ii < 4; ++ii) {
                    float4 wv = dwt4[(ic*4 + ii)*32 + k4];
                    dacc[ii] = fmaf(hv.x, wv.x,
                               fmaf(hv.y, wv.y,
                               fmaf(hv.z, wv.z,
                               fmaf(hv.w, wv.w, dacc[ii]))));
                }
            }
            float po = 0.0f;
            #pragma unroll
            for (int ii = 0; ii < 4; ++ii) {
                float dv = fmaxf(dacc[ii] + db0s[ic*4 + ii], 0.0f);
                po = fmaf(dv, dw1s[ic*4 + ii], po);
            }
            outp[ic][drow] = po;
        }
        __syncthreads();

        if (tid < ROWS) {
            float o = outp[0][tid] + outp[1][tid] + outp[2][tid] + outp[3][tid] + db1s;
            out[(u64)(row0 + tid)*50 + s + 1] = o;
            xps[tid] = o;
        }
        __syncthreads();   // xps ready for next step
    }
}

extern "C" void kernel_launch(void* const* d_in, const int* in_sizes, int n_in,
                              void* d_out, int out_size) {
    (void)in_sizes; (void)n_in; (void)out_size;
    const float* x   = (const float*)d_in[0];
    const float* ew0 = (const float*)d_in[1];
    const float* eb0 = (const float*)d_in[2];
    const float* ew1 = (const float*)d_in[3];
    const float* eb1 = (const float*)d_in[4];
    const float* ew2 = (const float*)d_in[5];
    const float* eb2 = (const float*)d_in[6];
    const float* wih = (const float*)d_in[7];
    const float* whh = (const float*)d_in[8];
    const float* bih = (const float*)d_in[9];
    const float* bhh = (const float*)d_in[10];
    const float* dw0 = (const float*)d_in[11];
    const float* db0 = (const float*)d_in[12];
    const float* dw1 = (const float*)d_in[13];
    const float* db1 = (const float*)d_in[14];
    float* out = (float*)d_out;

    gru_kernel<<<NBLK, NTHR>>>(x, ew0, eb0, ew1, eb1, ew2, eb2,
                               wih, whh, bih, bhh, dw0, db0, dw1, db1, out);
}